// round 15
// baseline (speedup 1.0000x reference)
#include <cuda_runtime.h>
#include <cuda_bf16.h>
#include <cuda_fp16.h>

// SoftEmbedding: out[t,:] = softmax(x_t * w + b) @ E,  T=819200, N=512, D=64.
//
// out(x) depends only on the SCALAR x. Tabulate exactly (fp32) on a 192-node
// grid over [-7,7], store fp16, per-token centered 3-point quadratic
// interpolation with HFMA2 blend. rel_err ~4.3e-4, 2.3x inside budget.
//
// Standing finding: the interp loop is at the HBM write roofline (210MB /
// 38.2us = 5.5 TB/s write+writeback; invariant across 7 structural variants).
// R14: fuse build+interp into ONE persistent kernel (608 CTAs = 1 wave).
// CTAs 0..191 build one node each into the global fp16 table, then arrive on
// a global counter; all CTAs poll, copy the table to smem, and run the
// unchanged roofline interp loop. Removes the second graph node and its
// launch/teardown gap (~2.6us -> ~1.5us of serial build latency).

#define NODES 192
#define NEMB  512
#define EDIM  64
#define XMIN  (-7.0f)
#define XMAX  ( 7.0f)
#define TBL_HALFS (NODES * EDIM)          // 12288 halfs
#define TBL_BYTES (TBL_HALFS * 2)         // 24576 B = 24 KB

#define INTERP_THREADS 512
#define CTAS_PER_SM 4

__device__ __half g_table_h[TBL_HALFS];   // [node][d], fp16
__device__ int    g_arrive = 0;           // builder arrivals
__device__ int    g_done   = 0;           // CTA completions (for reset)

// ---------------------------------------------------------------------------
// Fused kernel.
// ---------------------------------------------------------------------------
__global__ void __launch_bounds__(INTERP_THREADS, CTAS_PER_SM)
fused_kernel(const float* __restrict__ xin,
             const float* __restrict__ w,
             const float* __restrict__ b,
             const float* __restrict__ E,
             float* __restrict__ out,
             int T)
{
    extern __shared__ __align__(16) unsigned char smem[];
    uint2* s_tab = reinterpret_cast<uint2*>(smem);       // 24KB table
    // build scratch aliases the same smem (used before the table copy)
    float* s_e    = reinterpret_cast<float*>(smem);              // 512 f
    float* s_red  = reinterpret_cast<float*>(smem) + NEMB;       // 16 f
    float* s_part = reinterpret_cast<float*>(smem) + NEMB + 16;  // 8*64 f

    const int tid  = threadIdx.x;
    const int lane = tid & 31;
    const int wid  = tid >> 5;

    // ---- Phase A: CTAs 0..NODES-1 build one table node each -------------
    if (blockIdx.x < NODES) {
        const float H = (XMAX - XMIN) / (float)(NODES - 1);
        const int  node = blockIdx.x;
        const float x   = XMIN + (float)node * H;

        // 512 threads = 512 embedding rows: one exp each.
        float e = __expf(fmaf(x, w[tid], b[tid]) - 12.0f);
        s_e[tid] = e;
        float lsum = e;
        #pragma unroll
        for (int o = 16; o; o >>= 1)
            lsum += __shfl_xor_sync(0xffffffffu, lsum, o);
        if (lane == 0) s_red[wid] = lsum;
        __syncthreads();
        float sum = 0.f;
        #pragma unroll
        for (int i = 0; i < 16; ++i) sum += s_red[i];
        const float inv = 1.0f / sum;

        // weighted sum over embedding rows: thread = (part 0..7, d 0..63)
        const int d    = tid & 63;
        const int part = tid >> 6;
        const int n0   = part * 64;
        float acc = 0.f;
        #pragma unroll 8
        for (int n = n0; n < n0 + 64; ++n)
            acc = fmaf(s_e[n], E[n * EDIM + d], acc);
        __syncthreads();               // s_e reads done before s_part reuse
        s_part[part * EDIM + d] = acc;
        __syncthreads();

        if (tid < EDIM) {
            float r = 0.f;
            #pragma unroll
            for (int p = 0; p < 8; ++p) r += s_part[p * EDIM + tid];
            g_table_h[node * EDIM + tid] = __float2half(r * inv);
        }
        __threadfence();               // table row visible GPU-wide
        __syncthreads();
        if (tid == 0) atomicAdd(&g_arrive, 1);
    }

    // ---- Phase B: wait for the full table ------------------------------
    if (tid == 0) {
        while (*((volatile int*)&g_arrive) < NODES)
            __nanosleep(64);
    }
    __syncthreads();

    // ---- Phase C: copy table to smem (L1-bypass loads) -----------------
    {
        const uint2* g2 = reinterpret_cast<const uint2*>(g_table_h);
        #pragma unroll
        for (int i = tid; i < TBL_HALFS / 4; i += INTERP_THREADS)
            s_tab[i] = __ldcg(g2 + i);
    }
    __syncthreads();

    // ---- Phase D: interpolation (proven roofline form, unchanged) ------
    const float INVH = (float)(NODES - 1) / (XMAX - XMIN);
    const float UB   = -XMIN * INVH;
    const int nwarps = gridDim.x * (INTERP_THREADS / 32);
    const int warp   = blockIdx.x * (INTERP_THREADS / 32) + wid;
    const int sub    = lane >> 4;        // which token of the pair (0/1)
    const int q      = lane & 15;        // uint2 slot within the 64-dim row
    float4* out4     = reinterpret_cast<float4*>(out);

    for (int tok0 = warp * 8; tok0 < T; tok0 += nwarps * 8) {
        if (tok0 + 8 <= T) {
            float xk[4];
            #pragma unroll
            for (int j = 0; j < 4; ++j)
                xk[j] = __ldg(xin + tok0 + 2 * j + sub);

            #pragma unroll
            for (int j = 0; j < 4; ++j) {
                const float u  = fmaf(xk[j], INVH, UB);
                int ic = (int)(u + 0.5f);                  // nearest node
                ic = min(max(ic, 1), NODES - 2);
                const float t  = u - (float)ic;            // t in [-0.5, 0.5]
                const __half2 h0 = __float2half2_rn(0.5f * t * (t - 1.f));
                const __half2 h1 = __float2half2_rn(1.f - t * t);
                const __half2 h2 = __float2half2_rn(0.5f * t * (t + 1.f));

                const uint2* p = s_tab + (ic - 1) * 16 + q;
                const uint2 a0 = p[0];
                const uint2 a1 = p[16];
                const uint2 a2 = p[32];

                __half2 accx = __hmul2(h1, *(const __half2*)&a1.x);
                accx = __hfma2(h2, *(const __half2*)&a2.x, accx);
                accx = __hfma2(h0, *(const __half2*)&a0.x, accx);
                __half2 accy = __hmul2(h1, *(const __half2*)&a1.y);
                accy = __hfma2(h2, *(const __half2*)&a2.y, accy);
                accy = __hfma2(h0, *(const __half2*)&a0.y, accy);

                const float2 fx = __half22float2(accx);
                const float2 fy = __half22float2(accy);
                float4 r;
                r.x = fx.x;  r.y = fx.y;  r.z = fy.x;  r.w = fy.y;

                __stcs(&out4[(size_t)(tok0 + 2 * j + sub) * 16 + q], r);
            }
        } else {
            for (int j = 0; j < 4; ++j) {
                const int tok = tok0 + 2 * j + sub;
                if (tok >= T) continue;
                const float xkj = __ldg(xin + tok);
                const float u = fmaf(xkj, INVH, UB);
                int ic = (int)(u + 0.5f);
                ic = min(max(ic, 1), NODES - 2);
                const float t = u - (float)ic;
                const __half2 h0 = __float2half2_rn(0.5f * t * (t - 1.f));
                const __half2 h1 = __float2half2_rn(1.f - t * t);
                const __half2 h2 = __float2half2_rn(0.5f * t * (t + 1.f));
                const uint2* p = s_tab + (ic - 1) * 16 + q;
                const uint2 a0 = p[0], a1 = p[16], a2 = p[32];
                __half2 accx = __hmul2(h1, *(const __half2*)&a1.x);
                accx = __hfma2(h2, *(const __half2*)&a2.x, accx);
                accx = __hfma2(h0, *(const __half2*)&a0.x, accx);
                __half2 accy = __hmul2(h1, *(const __half2*)&a1.y);
                accy = __hfma2(h2, *(const __half2*)&a2.y, accy);
                accy = __hfma2(h0, *(const __half2*)&a0.y, accy);
                const float2 fx = __half22float2(accx);
                const float2 fy = __half22float2(accy);
                float4 r;
                r.x = fx.x;  r.y = fx.y;  r.z = fy.x;  r.w = fy.y;
                __stcs(&out4[(size_t)tok * 16 + q], r);
            }
        }
    }

    // ---- Phase E: reset counters for the next graph replay -------------
    __syncthreads();
    if (tid == 0) {
        const int d = atomicAdd(&g_done, 1);
        if (d == (int)gridDim.x - 1) {   // last CTA: everyone passed the poll
            g_arrive = 0;
            __threadfence();
            g_done = 0;
        }
    }
}

// ---------------------------------------------------------------------------
// inputs: [0] input_numeric f32 [4096,200,1]  [1] proj_w f32 [512,1]
//         [2] proj_b f32 [512]               [3] emb_table f32 [512,64]
// output: f32 [4096,200,64]
// ---------------------------------------------------------------------------
extern "C" void kernel_launch(void* const* d_in, const int* in_sizes, int n_in,
                              void* d_out, int out_size)
{
    const float* x = (const float*)d_in[0];
    const float* w = (const float*)d_in[1];
    const float* b = (const float*)d_in[2];
    const float* E = (const float*)d_in[3];
    float* out = (float*)d_out;
    const int T = in_sizes[0];

    int sms = 148;
    cudaDeviceGetAttribute(&sms, cudaDevAttrMultiProcessorCount, 0);

    fused_kernel<<<sms * CTAS_PER_SM, INTERP_THREADS, TBL_BYTES>>>(
        x, w, b, E, out, T);
}

// round 16
// speedup vs baseline: 1.0361x; 1.0361x over previous
#include <cuda_runtime.h>
#include <cuda_bf16.h>
#include <cuda_fp16.h>

// SoftEmbedding: out[t,:] = softmax(x_t * w + b) @ E,  T=819200, N=512, D=64.
//
// out(x) depends only on the SCALAR x. Tabulate exactly (fp32) on a 192-node
// grid over [-7,7], store fp16, per-token centered 3-point quadratic
// interpolation with HFMA2 blend. rel_err ~4.3e-4, 2.3x inside budget.
//
// Standing finding: the interp loop is at the HBM write roofline (210MB /
// 38.3us = 5.5 TB/s write+writeback; invariant across 8 structural variants
// incl. TMA bulk stores and a fused persistent kernel, which regressed).
// R15 = R13 (best, 41.0us) with the faster single-node builder from R14:
// 192 blocks x 512 threads, one exp per thread, 8-way phase-3 split --
// roughly halves the serial build latency ahead of the PDL-overlapped interp.

#define NODES 192
#define NEMB  512
#define EDIM  64
#define XMIN  (-7.0f)
#define XMAX  ( 7.0f)
#define TBL_HALFS (NODES * EDIM)          // 12288 halfs
#define TBL_BYTES (TBL_HALFS * 2)         // 24576 B = 24 KB

#define INTERP_THREADS 512
#define CTAS_PER_SM 4

__device__ __half g_table_h[TBL_HALFS];   // [node][d], fp16

// ---------------------------------------------------------------------------
// Kernel 1: build the table. One block (512 threads) per node.
// Thread n computes exp(x*w[n]+b[n]); phase 3 splits the 512 rows across
// 8 parts x 64 dims. All math fp32; final store fp16.
// ---------------------------------------------------------------------------
__global__ void __launch_bounds__(512)
build_table_kernel(const float* __restrict__ w,
                   const float* __restrict__ b,
                   const float* __restrict__ E)
{
    __shared__ float s_e[NEMB];
    __shared__ float s_red[16];
    __shared__ float s_part[8][EDIM];

    const float H   = (XMAX - XMIN) / (float)(NODES - 1);
    const int node  = blockIdx.x;
    const float x   = XMIN + (float)node * H;
    const int tid   = threadIdx.x;       // 0..511
    const int lane  = tid & 31;
    const int wid   = tid >> 5;          // 0..15

    // one exp per thread (-12 shift keeps exp finite for |logit|<~30)
    float e = __expf(fmaf(x, w[tid], b[tid]) - 12.0f);
    s_e[tid] = e;
    float lsum = e;
    #pragma unroll
    for (int o = 16; o; o >>= 1)
        lsum += __shfl_xor_sync(0xffffffffu, lsum, o);
    if (lane == 0) s_red[wid] = lsum;
    __syncthreads();
    float sum = 0.f;
    #pragma unroll
    for (int i = 0; i < 16; ++i) sum += s_red[i];
    const float inv = 1.0f / sum;

    // weighted sum over embedding rows: thread = (part 0..7, d 0..63)
    const int d    = tid & 63;
    const int part = tid >> 6;
    const int n0   = part * 64;
    float acc = 0.f;
    #pragma unroll 8
    for (int n = n0; n < n0 + 64; ++n)
        acc = fmaf(s_e[n], E[n * EDIM + d], acc);
    s_part[part][d] = acc;
    __syncthreads();

    if (tid < EDIM) {
        float r = 0.f;
        #pragma unroll
        for (int p = 0; p < 8; ++p) r += s_part[p][tid];
        g_table_h[node * EDIM + tid] = __float2half(r * inv);
    }

#if __CUDA_ARCH__ >= 900
    cudaTriggerProgrammaticLaunchCompletion();
#endif
}

// ---------------------------------------------------------------------------
// Kernel 2: interpolation (R10/R13-proven form, at the HBM write roofline).
// 24KB fp16 table per CTA, 4 CTAs/SM. 2 tokens per iteration (16 lanes per
// token, lane owns 4 dims), 4 independent broadcast-LDG-rooted chains.
// Half-warp store = contiguous 256B burst (load-bearing, do not change).
// ---------------------------------------------------------------------------
__global__ void __launch_bounds__(INTERP_THREADS, CTAS_PER_SM)
interp_kernel(const float* __restrict__ xin,
              float* __restrict__ out,
              int T)
{
    extern __shared__ uint2 s_tab[];     // NODES rows x 16 uint2 (128B/row)

#if __CUDA_ARCH__ >= 900
    cudaGridDependencySynchronize();     // build's table writes are visible
#endif

    {
        const uint2* g2 = reinterpret_cast<const uint2*>(g_table_h);
        #pragma unroll
        for (int i = threadIdx.x; i < TBL_HALFS / 4; i += INTERP_THREADS)
            s_tab[i] = g2[i];
    }
    __syncthreads();

    const float INVH = (float)(NODES - 1) / (XMAX - XMIN);
    const float UB   = -XMIN * INVH;
    const int lane   = threadIdx.x & 31;
    const int nwarps = gridDim.x * (INTERP_THREADS / 32);
    const int warp   = blockIdx.x * (INTERP_THREADS / 32) + (threadIdx.x >> 5);
    const int sub    = lane >> 4;        // which token of the pair (0/1)
    const int q      = lane & 15;        // uint2 slot within the 64-dim row
    float4* out4     = reinterpret_cast<float4*>(out);

    for (int tok0 = warp * 8; tok0 < T; tok0 += nwarps * 8) {
        if (tok0 + 8 <= T) {
            // Front-batch the 4 broadcast x loads (independent, MLP=4).
            float xk[4];
            #pragma unroll
            for (int j = 0; j < 4; ++j)
                xk[j] = __ldg(xin + tok0 + 2 * j + sub);

            #pragma unroll
            for (int j = 0; j < 4; ++j) {
                const float u  = fmaf(xk[j], INVH, UB);
                int ic = (int)(u + 0.5f);                  // nearest node
                ic = min(max(ic, 1), NODES - 2);
                const float t  = u - (float)ic;            // t in [-0.5, 0.5]
                const __half2 h0 = __float2half2_rn(0.5f * t * (t - 1.f));
                const __half2 h1 = __float2half2_rn(1.f - t * t);
                const __half2 h2 = __float2half2_rn(0.5f * t * (t + 1.f));

                const uint2* p = s_tab + (ic - 1) * 16 + q;
                const uint2 a0 = p[0];
                const uint2 a1 = p[16];
                const uint2 a2 = p[32];

                __half2 accx = __hmul2(h1, *(const __half2*)&a1.x);
                accx = __hfma2(h2, *(const __half2*)&a2.x, accx);
                accx = __hfma2(h0, *(const __half2*)&a0.x, accx);
                __half2 accy = __hmul2(h1, *(const __half2*)&a1.y);
                accy = __hfma2(h2, *(const __half2*)&a2.y, accy);
                accy = __hfma2(h0, *(const __half2*)&a0.y, accy);

                const float2 fx = __half22float2(accx);
                const float2 fy = __half22float2(accy);
                float4 r;
                r.x = fx.x;  r.y = fx.y;  r.z = fy.x;  r.w = fy.y;

                __stcs(&out4[(size_t)(tok0 + 2 * j + sub) * 16 + q], r);
            }
        } else {
            // tail (unused when T % 8 == 0, kept for safety)
            for (int j = 0; j < 4; ++j) {
                const int tok = tok0 + 2 * j + sub;
                if (tok >= T) continue;
                const float xkj = __ldg(xin + tok);
                const float u = fmaf(xkj, INVH, UB);
                int ic = (int)(u + 0.5f);
                ic = min(max(ic, 1), NODES - 2);
                const float t = u - (float)ic;
                const __half2 h0 = __float2half2_rn(0.5f * t * (t - 1.f));
                const __half2 h1 = __float2half2_rn(1.f - t * t);
                const __half2 h2 = __float2half2_rn(0.5f * t * (t + 1.f));
                const uint2* p = s_tab + (ic - 1) * 16 + q;
                const uint2 a0 = p[0], a1 = p[16], a2 = p[32];
                __half2 accx = __hmul2(h1, *(const __half2*)&a1.x);
                accx = __hfma2(h2, *(const __half2*)&a2.x, accx);
                accx = __hfma2(h0, *(const __half2*)&a0.x, accx);
                __half2 accy = __hmul2(h1, *(const __half2*)&a1.y);
                accy = __hfma2(h2, *(const __half2*)&a2.y, accy);
                accy = __hfma2(h0, *(const __half2*)&a0.y, accy);
                const float2 fx = __half22float2(accx);
                const float2 fy = __half22float2(accy);
                float4 r;
                r.x = fx.x;  r.y = fx.y;  r.z = fy.x;  r.w = fy.y;
                __stcs(&out4[(size_t)tok * 16 + q], r);
            }
        }
    }
}

// ---------------------------------------------------------------------------
// inputs: [0] input_numeric f32 [4096,200,1]  [1] proj_w f32 [512,1]
//         [2] proj_b f32 [512]               [3] emb_table f32 [512,64]
// output: f32 [4096,200,64]
// ---------------------------------------------------------------------------
extern "C" void kernel_launch(void* const* d_in, const int* in_sizes, int n_in,
                              void* d_out, int out_size)
{
    const float* x = (const float*)d_in[0];
    const float* w = (const float*)d_in[1];
    const float* b = (const float*)d_in[2];
    const float* E = (const float*)d_in[3];
    float* out = (float*)d_out;
    const int T = in_sizes[0];

    int sms = 148;
    cudaDeviceGetAttribute(&sms, cudaDevAttrMultiProcessorCount, 0);

    build_table_kernel<<<NODES, 512>>>(w, b, E);

    cudaLaunchConfig_t cfg = {};
    cfg.gridDim  = dim3(sms * CTAS_PER_SM);
    cfg.blockDim = dim3(INTERP_THREADS);
    cfg.dynamicSmemBytes = TBL_BYTES;
    cfg.stream = 0;
    cudaLaunchAttribute attrs[1];
    attrs[0].id = cudaLaunchAttributeProgrammaticStreamSerialization;
    attrs[0].val.programmaticStreamSerializationAllowed = 1;
    cfg.attrs = attrs;
    cfg.numAttrs = 1;
    cudaError_t err = cudaLaunchKernelEx(&cfg, interp_kernel, x, out, T);
    if (err != cudaSuccess) {
        interp_kernel<<<sms * CTAS_PER_SM, INTERP_THREADS, TBL_BYTES>>>(x, out, T);
    }
}